// round 2
// baseline (speedup 1.0000x reference)
#include <cuda_runtime.h>

// QConv1D quantum-circuit sim, restructured:
//  - RY(x) + RY(p_l0) layers fused analytically into a product state
//  - final CZ layer dropped (sign^2 = 1 under |amp|^2 measurement)
//  - one warp per flat sim index s = o*N_POS + b*L_OUT + pos; 256 amps = 8 regs/lane
//  - output address replicates the reference's reshape reinterpretation:
//    flat buffer [o][b][pos] read back as [b'][pos'][o']
constexpr int O_CH  = 8;
constexpr int NQ    = 8;
constexpr int C_IN  = 2;
constexpr int KW    = 4;
constexpr int B_SZ  = 16;
constexpr int L_IN  = 512;
constexpr int L_OUT = L_IN - (KW - 1);   // 509
constexpr int N_POS = B_SZ * L_OUT;      // 8144
constexpr int NSIM  = N_POS * O_CH;      // 65152

__global__ __launch_bounds__(256)
void qconv_kernel(const float* __restrict__ x,
                  const float* __restrict__ w,
                  float* __restrict__ out)
{
    const int s = (blockIdx.x * blockDim.x + threadIdx.x) >> 5;
    if (s >= NSIM) return;
    const int lane = threadIdx.x & 31;

    // --- simulation-side decomposition: s = o_sim * N_POS + b_sim * L_OUT + pos_sim
    const int o_sim   = s / N_POS;
    const int n       = s - o_sim * N_POS;
    const int b_sim   = n / L_OUT;
    const int pos_sim = n - b_sim * L_OUT;

    // Lane q (<8) computes trig for qubit q:
    //   combined angle (x_q + p_{q,0})/2  -> (c1,s1)
    //   layer-1 param  p_{q,1}/2          -> (c2,s2)
    float c1 = 0.f, s1 = 0.f, c2 = 0.f, s2 = 0.f;
    if (lane < NQ) {
        const int ci = lane >> 2;   // q / K
        const int k  = lane & 3;    // q % K
        const float xv = x[(b_sim * C_IN + ci) * L_IN + pos_sim + k];
        const float p0 = w[(o_sim * NQ + lane) * 2 + 0];
        const float p1 = w[(o_sim * NQ + lane) * 2 + 1];
        sincosf(0.5f * (xv + p0), &s1, &c1);
        sincosf(0.5f * p1,        &s2, &c2);
    }

    // Broadcast product-state trig to all lanes.
    float cs[NQ], ss[NQ];
#pragma unroll
    for (int q = 0; q < NQ; q++) {
        cs[q] = __shfl_sync(0xffffffffu, c1, q);
        ss[q] = __shfl_sync(0xffffffffu, s1, q);
    }

    // amplitude index b = (lane << 3) | r ; bit j of b <-> qubit (7 - j)
    // base: lane bits i = 0..4  (b bits 3..7, qubits 4..0)
    float base = 1.f;
#pragma unroll
    for (int i = 0; i < 5; i++)
        base *= ((lane >> i) & 1) ? ss[4 - i] : cs[4 - i];

    // 8 amplitudes per lane: product state * CZ sign (-1)^popc(b & b>>1)
    float a[8];
#pragma unroll
    for (int r = 0; r < 8; r++) {
        const float f = ((r & 1) ? ss[7] : cs[7])
                      * ((r & 2) ? ss[6] : cs[6])
                      * ((r & 4) ? ss[5] : cs[5]);
        const int b = (lane << 3) | r;
        const float sgn = (__popc(b & (b >> 1)) & 1) ? -1.f : 1.f;
        a[r] = base * f * sgn;
    }

    // Layer-1 RYs applied to the full (entangled) state.
    // bit j: j<3 in-register pairs, j>=3 via shfl_xor on lane bit (j-3).
#pragma unroll
    for (int j = 0; j < 8; j++) {
        const float c = __shfl_sync(0xffffffffu, c2, 7 - j);
        const float sA = __shfl_sync(0xffffffffu, s2, 7 - j);
        if (j < 3) {
            const int m = 1 << j;
#pragma unroll
            for (int r = 0; r < 8; r++) {
                if (!(r & m)) {
                    const float a0 = a[r], a1 = a[r | m];
                    a[r]     = fmaf(-sA, a1, c * a0);
                    a[r | m] = fmaf( sA, a0, c * a1);
                }
            }
        } else {
            const int m = 1 << (j - 3);
            const float sv = ((lane >> (j - 3)) & 1) ? sA : -sA;
#pragma unroll
            for (int r = 0; r < 8; r++) {
                const float p = __shfl_xor_sync(0xffffffffu, a[r], m);
                a[r] = fmaf(sv, p, c * a[r]);
            }
        }
    }

    // <Z...Z> = sum (-1)^popc(b) * amp^2 ; popc(b) = popc(lane)^popc(r)
    // per-r parity signs for r=0..7: + - - + - + + -
    float acc = a[0]*a[0] - a[1]*a[1] - a[2]*a[2] + a[3]*a[3]
              - a[4]*a[4] + a[5]*a[5] + a[6]*a[6] - a[7]*a[7];
    if (__popc(lane) & 1) acc = -acc;
#pragma unroll
    for (int m = 16; m >= 1; m >>= 1)
        acc += __shfl_xor_sync(0xffffffffu, acc, m);

    // --- output-side reinterpretation of flat index s as [b'][pos'][o']
    if (lane == 0) {
        const int o_out = s & (O_CH - 1);
        const int t     = s >> 3;            // = b'*L_OUT + pos'
        const int b_out = t / L_OUT;
        const int p_out = t - b_out * L_OUT;
        out[(b_out * O_CH + o_out) * L_OUT + p_out] = acc;
    }
}

extern "C" void kernel_launch(void* const* d_in, const int* in_sizes, int n_in,
                              void* d_out, int out_size)
{
    const float* x = (const float*)d_in[0];
    const float* w = (const float*)d_in[1];
    float* out = (float*)d_out;
    const int threads = 256;
    const int wpb = threads / 32;
    const int blocks = (NSIM + wpb - 1) / wpb;   // 8144, exact
    qconv_kernel<<<blocks, threads>>>(x, w, out);
}

// round 3
// speedup vs baseline: 1.3393x; 1.3393x over previous
#include <cuda_runtime.h>

// QConv1D quantum sim, R3:
//  - layer0 (x + p0) fused analytically into product state (RY(a)RY(b)=RY(a+b))
//  - final CZ layer dropped (|amp|^2 measurement)
//  - weight trig precomputed once in a setup kernel (__device__ table)
//  - TWO sims per warp packed into f32x2 lanes (same o, adjacent positions):
//    all FMA/ALU ops elementwise across the pair -> per-sim flop count halves
typedef unsigned long long u64;

constexpr int O_CH  = 8;
constexpr int NQ    = 8;
constexpr int C_IN  = 2;
constexpr int L_IN  = 512;
constexpr int L_OUT = 509;
constexpr int N_POS = 16 * L_OUT;     // 8144
constexpr int NPAIR = N_POS / 2;      // 4072
constexpr int NWARP = O_CH * NPAIR;   // 32576

__device__ float2 g_wt0[O_CH * NQ];   // {cos(p0/2), sin(p0/2)}
__device__ float2 g_wt1[O_CH * NQ];   // {cos(p1/2), sin(p1/2)}

__global__ void wtrig_kernel(const float* __restrict__ w) {
    int i = threadIdx.x;
    if (i < O_CH * NQ) {
        float c0, s0, c1, s1;
        sincosf(0.5f * w[i * 2 + 0], &s0, &c0);
        sincosf(0.5f * w[i * 2 + 1], &s1, &c1);
        g_wt0[i] = make_float2(c0, s0);
        g_wt1[i] = make_float2(c1, s1);
    }
}

__device__ __forceinline__ u64 pk2(float lo, float hi) {
    u64 r; asm("mov.b64 %0,{%1,%2};" : "=l"(r) : "f"(lo), "f"(hi)); return r;
}
__device__ __forceinline__ void upk2(u64 v, float& lo, float& hi) {
    asm("mov.b64 {%0,%1},%2;" : "=f"(lo), "=f"(hi) : "l"(v));
}
__device__ __forceinline__ u64 dup2(float v) { return pk2(v, v); }
__device__ __forceinline__ u64 mul2(u64 a, u64 b) {
    u64 r; asm("mul.rn.f32x2 %0,%1,%2;" : "=l"(r) : "l"(a), "l"(b)); return r;
}
__device__ __forceinline__ u64 fma2(u64 a, u64 b, u64 c) {
    u64 r; asm("fma.rn.f32x2 %0,%1,%2,%3;" : "=l"(r) : "l"(a), "l"(b), "l"(c)); return r;
}
__device__ __forceinline__ u64 add2(u64 a, u64 b) {
    u64 r; asm("add.rn.f32x2 %0,%1,%2;" : "=l"(r) : "l"(a), "l"(b)); return r;
}
__device__ __forceinline__ u64 neg2(u64 a) { return a ^ 0x8000000080000000ull; }
__device__ __forceinline__ u64 shflx2(u64 a, int m) {
    float lo, hi; upk2(a, lo, hi);
    lo = __shfl_xor_sync(0xffffffffu, lo, m);
    hi = __shfl_xor_sync(0xffffffffu, hi, m);
    return pk2(lo, hi);
}

__global__ __launch_bounds__(256)
void qconv_kernel(const float* __restrict__ x, float* __restrict__ out)
{
    const int wp = (blockIdx.x * blockDim.x + threadIdx.x) >> 5;
    const int lane = threadIdx.x & 31;
    const int o = wp / NPAIR;
    const int t = wp - o * NPAIR;
    const int nA = 2 * t;              // sim A: (o, nA); sim B: (o, nA+1)

    // lanes 0..7: sim A trig for qubit q=lane; lanes 8..15: sim B, q=lane-8
    float c1 = 0.f, s1 = 0.f;
    if (lane < 16) {
        const int q   = lane & 7;
        const int n   = (lane < 8) ? nA : nA + 1;
        const int bb  = n / L_OUT;
        const int pos = n - bb * L_OUT;
        const float xv = x[(bb * C_IN + (q >> 2)) * L_IN + pos + (q & 3)];
        float sx, cx;
        __sincosf(0.5f * xv, &sx, &cx);
        const float2 w0 = g_wt0[o * NQ + q];
        c1 = cx * w0.x - sx * w0.y;    // cos((x+p0)/2)
        s1 = sx * w0.x + cx * w0.y;    // sin((x+p0)/2)
    }

    // broadcast + pack product-state trig: (simA, simB) per qubit
    u64 cs[NQ], ss[NQ];
#pragma unroll
    for (int q = 0; q < NQ; q++) {
        cs[q] = pk2(__shfl_sync(0xffffffffu, c1, q), __shfl_sync(0xffffffffu, c1, q + 8));
        ss[q] = pk2(__shfl_sync(0xffffffffu, s1, q), __shfl_sync(0xffffffffu, s1, q + 8));
    }

    // amplitude index b = (lane<<3)|r ; b bit j <-> qubit 7-j
    // base over lane bits 0..4 -> qubits 4..0
    u64 base = (lane & 1) ? ss[4] : cs[4];
#pragma unroll
    for (int i = 1; i < 5; i++)
        base = mul2(base, ((lane >> i) & 1) ? ss[4 - i] : cs[4 - i]);

    // CZ sign (-1)^popc(b & b>>1) = pl ^ pr(r) ^ ((lane&1)&(r>>2))
    // pl: lane-internal adjacencies; pr(r): compile-time; cross term folded into r>=4 base.
    const int pl = __popc(lane & (lane >> 1)) & 1;
    const u64 bp  = pl ? neg2(base) : base;              // r<4, pr=0
    const u64 bp4 = (pl ^ (lane & 1)) ? neg2(base) : base; // r>=4, pr=0
    const u64 bn  = neg2(bp);                            // r<4, pr=1
    const u64 bn4 = neg2(bp4);                           // r>=4, pr=1

    // f(r) = (r&1?ss7:cs7)*(r&2?ss6:cs6)*(r&4?ss5:cs5); share middle/high factors
    u64 g[4];
    g[0] = mul2(cs[6], cs[5]);
    g[1] = mul2(ss[6], cs[5]);
    g[2] = mul2(cs[6], ss[5]);
    g[3] = mul2(ss[6], ss[5]);

    u64 a[8];
    // pr(r): r=3,6 -> 1; else 0
    a[0] = mul2(mul2(cs[7], g[0]), bp);
    a[1] = mul2(mul2(ss[7], g[0]), bp);
    a[2] = mul2(mul2(cs[7], g[1]), bp);
    a[3] = mul2(mul2(ss[7], g[1]), bn);
    a[4] = mul2(mul2(cs[7], g[2]), bp4);
    a[5] = mul2(mul2(ss[7], g[2]), bp4);
    a[6] = mul2(mul2(cs[7], g[3]), bn4);
    a[7] = mul2(mul2(ss[7], g[3]), bp4);

    // layer-1 RYs. b bit j: j<3 in-register (r bit j), j>=3 cross-lane (lane bit j-3).
    // qubit index = 7-j; coefficients uniform per warp (same o for both sims).
#pragma unroll
    for (int j = 0; j < 3; j++) {
        const float2 w1 = g_wt1[o * NQ + 7 - j];
        const u64 c  = dup2(w1.x);
        const u64 s  = dup2(w1.y);
        const u64 ns = neg2(s);
        const int m = 1 << j;
#pragma unroll
        for (int r = 0; r < 8; r++) {
            if (!(r & m)) {
                const u64 a0 = a[r], a1 = a[r | m];
                a[r]     = fma2(ns, a1, mul2(c, a0));
                a[r | m] = fma2(s,  a0, mul2(c, a1));
            }
        }
    }
#pragma unroll
    for (int j = 3; j < 8; j++) {
        const float2 w1 = g_wt1[o * NQ + 7 - j];
        const u64 c = dup2(w1.x);
        const float sv = ((lane >> (j - 3)) & 1) ? w1.y : -w1.y;
        const u64 s2v = dup2(sv);
        const int m = 1 << (j - 3);
#pragma unroll
        for (int r = 0; r < 8; r++) {
            const u64 p = shflx2(a[r], m);
            a[r] = fma2(s2v, p, mul2(c, a[r]));
        }
    }

    // <Z..Z> = sum (-1)^popc(b) amp^2 ; per-r sign pattern + - - + - + + -, flipped by parity(lane)
    u64 accp = mul2(a[0], a[0]);
    accp = fma2(a[3], a[3], accp);
    accp = fma2(a[5], a[5], accp);
    accp = fma2(a[6], a[6], accp);
    u64 accn = mul2(a[1], a[1]);
    accn = fma2(a[2], a[2], accn);
    accn = fma2(a[4], a[4], accn);
    accn = fma2(a[7], a[7], accn);
    u64 acc = add2(accp, neg2(accn));
    if (__popc(lane) & 1) acc = neg2(acc);

#pragma unroll
    for (int m = 16; m >= 1; m >>= 1)
        acc = add2(acc, shflx2(acc, m));

    if (lane == 0) {
        float rA, rB; upk2(acc, rA, rB);
        // reference's reshape reinterpretation: flat [o][n] read back as [b'][p'][o']
        const int sA = o * N_POS + nA;
#pragma unroll
        for (int k = 0; k < 2; k++) {
            const int s  = sA + k;
            const int oo = s & 7;
            const int tt = s >> 3;
            const int bo = tt / L_OUT;
            const int po = tt - bo * L_OUT;
            out[(bo * O_CH + oo) * L_OUT + po] = (k == 0) ? rA : rB;
        }
    }
}

extern "C" void kernel_launch(void* const* d_in, const int* in_sizes, int n_in,
                              void* d_out, int out_size)
{
    const float* x = (const float*)d_in[0];
    const float* w = (const float*)d_in[1];
    float* out = (float*)d_out;
    wtrig_kernel<<<1, 64>>>(w);
    const int threads = 256;                  // 8 warps
    const int blocks  = NWARP / 8;            // 4072, exact
    qconv_kernel<<<blocks, threads>>>(x, out);
}

// round 4
// speedup vs baseline: 3.5978x; 2.6863x over previous
#include <cuda_runtime.h>

// QConv1D quantum sim, R4: closed-form via Heisenberg conjugation.
// E = sum over independent sets S of the 8-qubit chain of
//     prod_{q in S} (-sin p1_q * sin(x_q+p0_q))
//   * prod_{q notin S} cos p1_q * (exactly-one-S-neighbor ? 1 : cos(x_q+p0_q))
// computed with a 3-state transfer-matrix DP. One THREAD per sim.
constexpr int O_CH  = 8;
constexpr int NQ    = 8;
constexpr int L_IN  = 512;
constexpr int L_OUT = 509;
constexpr int B_SZ  = 16;
constexpr int N_POS = B_SZ * L_OUT;          // 8144
constexpr int NX    = B_SZ * 2 * L_IN;       // 16384 x elements

__device__ float2 g_xtrig[NX];               // {cos x, sin x}
__device__ float4 g_w[O_CH * NQ];            // {cos p0, sin p0, cos p1, sin p1}

__global__ __launch_bounds__(256)
void setup_kernel(const float* __restrict__ x, const float* __restrict__ w)
{
    const int i = blockIdx.x * blockDim.x + threadIdx.x;
    if (i < NX) {
        float s, c;
        sincosf(x[i], &s, &c);
        g_xtrig[i] = make_float2(c, s);
    }
    if (i < O_CH * NQ) {
        float s0, c0, s1, c1;
        sincosf(w[i * 2 + 0], &s0, &c0);   // p0 (layer 0)
        sincosf(w[i * 2 + 1], &s1, &c1);   // p1 (layer 1)
        g_w[i] = make_float4(c0, s0, c1, s1);
    }
}

__global__ __launch_bounds__(256)
void sim_kernel(float* __restrict__ out)
{
    const int n = blockIdx.x * blockDim.x + threadIdx.x;   // position index
    if (n >= N_POS) return;
    const int o   = blockIdx.y;                            // out-channel
    const int bb  = n / L_OUT;
    const int pos = n - bb * L_OUT;

    const float2* __restrict__ xt0 = g_xtrig + (bb * 2 + 0) * L_IN + pos; // ch 0, k=0..3
    const float2* __restrict__ xt1 = g_xtrig + (bb * 2 + 1) * L_IN + pos; // ch 1, k=0..3
    const float4* __restrict__ wv  = g_w + o * NQ;

    // DP state over (b_{q-1}, b_q): v00, v01, v10  (b=1 means q in S)
    float v00 = 1.f, v01 = 1.f, v10 = 0.f;
#pragma unroll
    for (int q = 0; q < NQ; q++) {
        const float2 xt = (q < 4) ? xt0[q] : xt1[q - 4];
        const float4 wq = wv[q];
        // angle addition: C = cos(x+p0), S = sin(x+p0)
        const float C = xt.x * wq.x - xt.y * wq.y;
        const float S = xt.y * wq.x + xt.x * wq.y;
        const float u = -wq.w * S;                 // -sin(p1) * sin(x+p0)
        const float n00 = wq.z * fmaf(v00, C, v10);  // cos(p1)*(v00*C + v10)
        const float n01 = wq.z * fmaf(v10, C, v00);  // cos(p1)*(v00 + v10*C)
        const float n10 = u * v01;
        v00 = n00; v01 = n01; v10 = n10;
    }
    const float E = v00 + v10;   // boundary b_8 = 0

    // reference reshape reinterpretation: flat [o][n] read back as [b'][p'][o']
    const int s  = o * N_POS + n;
    const int oo = s & 7;
    const int tt = s >> 3;
    const int bo = tt / L_OUT;
    const int po = tt - bo * L_OUT;
    out[(bo * O_CH + oo) * L_OUT + po] = E;
}

extern "C" void kernel_launch(void* const* d_in, const int* in_sizes, int n_in,
                              void* d_out, int out_size)
{
    const float* x = (const float*)d_in[0];
    const float* w = (const float*)d_in[1];
    float* out = (float*)d_out;

    setup_kernel<<<(NX + 255) / 256, 256>>>(x, w);
    dim3 grid((N_POS + 255) / 256, O_CH);   // 32 x 8 blocks
    sim_kernel<<<grid, 256>>>(out);
}